// round 13
// baseline (speedup 1.0000x reference)
#include <cuda_runtime.h>
#include <stdint.h>

// ---------------------------------------------------------------------------
// TripletContrastiveLoss — tf32 mma.sync, 128x128 tile, occ-2, 3-stage
// cp.async ring with R10's proven prefetch-FIRST ordering, permuted-K layout
// + LDS.64 fragments. (tcgen05 unavailable: bench PTX targets compute_103.)
// ---------------------------------------------------------------------------

#define BMAX 8192
#define DMAX 1024
#define INFBITS 0x7f800000u

#define BM 128
#define BN 128
#define BK 32
#define ASTR 36      // row stride (floats); LDS.64 start-banks 2x per even residue
#define NTHR 256
#define STG_BYTES (BM * ASTR * 4)              // 18432 B per matrix per stage
#define SMEM4_BYTES (6 * STG_BYTES + BN * 4)   // 3 stages x (A+B) + labels = 111104 B

// K-permutation: each 8-float K-group stored as (k0,k4,k1,k5,k2,k6,k3,k7);
// mma fragment pair (k, k+4) sits at float offset g*8 + 2*(k%4), 8B-contiguous.
__device__ float g_A[(size_t)BMAX * DMAX];   // normalized anchors (tf32, K-permuted)
__device__ float g_F[(size_t)BMAX * DMAX];   // normalized fields  (tf32, K-permuted)
__device__ int   g_aRow[BMAX];
__device__ int   g_fRow[BMAX];
__device__ int   g_aLab[BMAX];
__device__ int   g_fLab[BMAX];
__device__ int   g_aCnt;
__device__ int   g_fCnt;
__device__ unsigned g_posBits[BMAX];
__device__ unsigned g_negBits[BMAX];
__device__ int   g_is64;

__device__ __forceinline__ uint32_t smem_u32(const void* p) {
    uint32_t a;
    asm("{ .reg .u64 t; cvta.to.shared.u64 t, %1; cvt.u32.u64 %0, t; }"
        : "=r"(a) : "l"(p));
    return a;
}
__device__ __forceinline__ void cpa16(uint32_t dst, const void* src) {
    asm volatile("cp.async.cg.shared.global [%0], [%1], 16;"
                 :: "r"(dst), "l"(src));
}

// ---- K0: reset scalars --------------------------------------------------
__global__ void k0_reset() {
    g_aCnt = 0;
    g_fCnt = 0;
    g_is64 = 1;
}

// ---- K1: init min arrays + label dtype detection ------------------------
// int64 labels (<2^31): every odd 32-bit word is 0. int32: some odd word !=0.
__global__ void k1_init_detect(const unsigned* __restrict__ labw, int B) {
    int i = blockIdx.x * blockDim.x + threadIdx.x;
    if (i < B) {
        g_posBits[i] = INFBITS;
        g_negBits[i] = INFBITS;
        if ((i & 1) && labw[i] != 0u) g_is64 = 0;
    }
}

// ---- K2: partition into compact anchor/field lists ----------------------
__global__ void k2_partition(const void* __restrict__ labels,
                             const void* __restrict__ doms, int B) {
    int i = blockIdx.x * blockDim.x + threadIdx.x;
    if (i >= B) return;
    int is64 = g_is64;
    long long dom, lab;
    if (is64) {
        dom = ((const long long*)doms)[i];
        lab = ((const long long*)labels)[i];
    } else {
        dom = ((const int*)doms)[i];
        lab = ((const int*)labels)[i];
    }
    if (dom == 0) {
        int p = atomicAdd(&g_aCnt, 1);
        g_aRow[p] = i;
        g_aLab[p] = (int)lab;
    } else if (dom == 1) {
        int p = atomicAdd(&g_fCnt, 1);
        g_fRow[p] = i;
        g_fLab[p] = (int)lab;
    }
}

// ---- K3: normalize + tf32 round + K-permute, one warp per row -----------
// Coalesced reads/writes; even/odd lane pairs swap float4s via shfl so each
// lane emits the permuted float4 for its own (coalesced) output slot.
__global__ void k3_normalize(const float* __restrict__ feat, int D) {
    int side = blockIdx.y;
    int n = side ? g_fCnt : g_aCnt;
    int warp = threadIdx.x >> 5;
    int lane = threadIdx.x & 31;
    int b = blockIdx.x * 8 + warp;
    if (b >= n) return;
    int row = side ? g_fRow[b] : g_aRow[b];
    const float4* src = (const float4*)(feat + (size_t)row * D);
    uint4* dst = (uint4*)((side ? g_F : g_A) + (size_t)b * D);
    int nv = D >> 2;                  // <= 256 float4 slots

    float4 v[8];
    float s = 0.f;
    #pragma unroll
    for (int j = 0; j < 8; j++) {
        int t = lane + j * 32;
        if (t < nv) {
            v[j] = src[t];
            s += v[j].x * v[j].x + v[j].y * v[j].y +
                 v[j].z * v[j].z + v[j].w * v[j].w;
        }
    }
    #pragma unroll
    for (int o = 16; o; o >>= 1) s += __shfl_xor_sync(0xffffffffu, s, o);
    float scale = 1.f / fmaxf(sqrtf(s), 1e-12f);

    const bool even = (lane & 1) == 0;
    #pragma unroll
    for (int j = 0; j < 8; j++) {
        int t = lane + j * 32;
        if (t < nv) {
            float4 p;
            p.x = __shfl_xor_sync(0xffffffffu, v[j].x, 1);
            p.y = __shfl_xor_sync(0xffffffffu, v[j].y, 1);
            p.z = __shfl_xor_sync(0xffffffffu, v[j].z, 1);
            p.w = __shfl_xor_sync(0xffffffffu, v[j].w, 1);
            float4 e  = even ? v[j] : p;   // group k0..k3
            float4 o4 = even ? p : v[j];   // group k4..k7
            float f0 = even ? e.x : e.z;
            float f1 = even ? o4.x : o4.z;
            float f2 = even ? e.y : e.w;
            float f3 = even ? o4.y : o4.w;
            uint4 o;
            asm("cvt.rna.tf32.f32 %0, %1;" : "=r"(o.x) : "f"(f0 * scale));
            asm("cvt.rna.tf32.f32 %0, %1;" : "=r"(o.y) : "f"(f1 * scale));
            asm("cvt.rna.tf32.f32 %0, %1;" : "=r"(o.z) : "f"(f2 * scale));
            asm("cvt.rna.tf32.f32 %0, %1;" : "=r"(o.w) : "f"(f3 * scale));
            dst[t] = o;
        }
    }
}

// ---- tf32 mma.sync wrapper ------------------------------------------------
__device__ __forceinline__ void mma_tf32(float* d, uint32_t a0, uint32_t a1,
                                         uint32_t a2, uint32_t a3,
                                         uint32_t b0, uint32_t b1) {
    asm volatile(
        "mma.sync.aligned.m16n8k8.row.col.f32.tf32.tf32.f32 "
        "{%0,%1,%2,%3}, {%4,%5,%6,%7}, {%8,%9}, {%0,%1,%2,%3};"
        : "+f"(d[0]), "+f"(d[1]), "+f"(d[2]), "+f"(d[3])
        : "r"(a0), "r"(a1), "r"(a2), "r"(a3), "r"(b0), "r"(b1));
}

// ---- K4: 128x128 HMMA tf32 GEMM, 3-stage ring (R10 ordering), fused min --
// 8 warps: warp grid 2(M)x4(N), warp tile 64x32 = 4x4 m16n8k8 atoms.
// Per chunk: prefetch c+2 -> commit -> wait_group 2 -> sync -> compute -> sync.
__global__ void __launch_bounds__(NTHR, 2)
k4_mma_min(int D) {
    extern __shared__ float smem[];
    float* sA = smem;                       // 3 stages of A
    float* sB = smem + 3 * (BM * ASTR);     // 3 stages of B
    int* sFlab = (int*)(smem + 6 * (BM * ASTR));

    const int NA = g_aCnt;
    const int NF = g_fCnt;
    const int by = blockIdx.y, bx = blockIdx.x;
    if (by * BM >= NA || bx * BN >= NF) return;

    const int tid = threadIdx.x;
    const int wid = tid >> 5;
    const int lane = tid & 31;
    const int qid = lane >> 2;
    const int qlane = lane & 3;
    const int wm = (wid & 1) * 64;
    const int wn = (wid >> 1) * 32;

    if (tid < BN) {
        int f = bx * BN + tid;
        sFlab[tid] = (f < NF) ? g_fLab[f] : -1;
    }

    // epilogue labels hoisted before the mainloop
    int al[4][2];
    #pragma unroll
    for (int mi = 0; mi < 4; mi++)
        #pragma unroll
        for (int h = 0; h < 2; h++) {
            int a_ = by * BM + wm + mi * 16 + qid + h * 8;
            al[mi][h] = (a_ < NA) ? g_aLab[a_] : -2;
        }

    // load geometry: thread covers rows m0+32*it (it=0..3), 16B column q4
    const int m0 = tid >> 3;        // 0..31
    const int q4 = (tid & 7) * 4;   // 0,4,...,28 (floats)
    int aRowG[4], bRowG[4];
    #pragma unroll
    for (int it = 0; it < 4; it++) {
        int ga = by * BM + m0 + 32 * it;
        aRowG[it] = (ga < NA) ? ga : NA - 1;   // clamp; rows >= NA unused
        int gf = bx * BN + m0 + 32 * it;
        bRowG[it] = (gf < NF) ? gf : NF - 1;   // clamp; excluded via sFlab
    }
    const uint32_t saB = smem_u32(sA);
    const uint32_t sbB = smem_u32(sB);
    const uint32_t dstOff = (uint32_t)((m0 * ASTR + q4) * 4);

    float acc[4][4][4];
    #pragma unroll
    for (int mi = 0; mi < 4; mi++)
        #pragma unroll
        for (int ni = 0; ni < 4; ni++)
            #pragma unroll
            for (int r = 0; r < 4; r++) acc[mi][ni][r] = 0.f;

    const int nch = D >> 5;

    // prologue: chunk 0 -> stage 0, chunk 1 -> stage 1 (one group each)
    #pragma unroll
    for (int it = 0; it < 4; it++) {
        cpa16(saB + dstOff + it * (32 * ASTR * 4),
              &g_A[(size_t)aRowG[it] * D + q4]);
        cpa16(sbB + dstOff + it * (32 * ASTR * 4),
              &g_F[(size_t)bRowG[it] * D + q4]);
    }
    asm volatile("cp.async.commit_group;");
    #pragma unroll
    for (int it = 0; it < 4; it++) {
        cpa16(saB + STG_BYTES + dstOff + it * (32 * ASTR * 4),
              &g_A[(size_t)aRowG[it] * D + q4 + 32]);
        cpa16(sbB + STG_BYTES + dstOff + it * (32 * ASTR * 4),
              &g_F[(size_t)bRowG[it] * D + q4 + 32]);
    }
    asm volatile("cp.async.commit_group;");

    // rotating stage offsets: stCur holds chunk c; stNN receives chunk c+2
    uint32_t stCur = 0, stNxt = STG_BYTES, stNN = 2 * STG_BYTES;

    for (int c = 0; c < nch; c++) {
        // prefetch FIRST (R10 ordering): chunk c+2 -> stNN (held c-1, whose
        // compute finished before iter c-1's trailing barrier)
        if (c + 2 < nch) {
            const int ko = (c + 2) << 5;
            #pragma unroll
            for (int it = 0; it < 4; it++) {
                cpa16(saB + stNN + dstOff + it * (32 * ASTR * 4),
                      &g_A[(size_t)aRowG[it] * D + q4 + ko]);
                cpa16(sbB + stNN + dstOff + it * (32 * ASTR * 4),
                      &g_F[(size_t)bRowG[it] * D + q4 + ko]);
            }
        }
        asm volatile("cp.async.commit_group;");   // empty group ok near the end
        asm volatile("cp.async.wait_group 2;");   // chunk c (2 commits ago) done
        __syncthreads();

        const float* cA = (const float*)((const char*)sA + stCur);
        const float* cB = (const float*)((const char*)sB + stCur);
        #pragma unroll
        for (int g = 0; g < 4; g++) {
            const int kb2 = g * 8 + 2 * qlane;    // permuted offset of (k, k+4)
            uint32_t a[4][4], b[4][2];
            #pragma unroll
            for (int mi = 0; mi < 4; mi++) {
                const float* pr = cA + (wm + mi * 16 + qid) * ASTR + kb2;
                uint2 lo = *(const uint2*)pr;                  // a0, a2
                uint2 hi = *(const uint2*)(pr + 8 * ASTR);     // a1, a3
                a[mi][0] = lo.x; a[mi][1] = hi.x;
                a[mi][2] = lo.y; a[mi][3] = hi.y;
            }
            #pragma unroll
            for (int ni = 0; ni < 4; ni++) {
                const float* pr = cB + (wn + ni * 8 + qid) * ASTR + kb2;
                uint2 bb = *(const uint2*)pr;                  // b0, b1
                b[ni][0] = bb.x; b[ni][1] = bb.y;
            }
            #pragma unroll
            for (int mi = 0; mi < 4; mi++)
                #pragma unroll
                for (int ni = 0; ni < 4; ni++)
                    mma_tf32(acc[mi][ni], a[mi][0], a[mi][1], a[mi][2], a[mi][3],
                             b[ni][0], b[ni][1]);
        }
        __syncthreads();   // fragment reads done before stage reuse

        // rotate stages
        uint32_t t = stCur; stCur = stNxt; stNxt = stNN; stNN = t;
    }

    // --- epilogue: d^2 = max(2 - 2*dot, 0), masked min per anchor row ----
    float posm[4][2], negm[4][2];
    #pragma unroll
    for (int mi = 0; mi < 4; mi++)
        #pragma unroll
        for (int h = 0; h < 2; h++) {
            posm[mi][h] = __uint_as_float(INFBITS);
            negm[mi][h] = posm[mi][h];
        }

    #pragma unroll
    for (int mi = 0; mi < 4; mi++) {
        #pragma unroll
        for (int ni = 0; ni < 4; ni++) {
            int n0 = wn + ni * 8 + 2 * qlane;
            int fl0 = sFlab[n0];
            int fl1 = sFlab[n0 + 1];
            #pragma unroll
            for (int h = 0; h < 2; h++) {
                float d20 = fmaxf(fmaf(-2.f, acc[mi][ni][h * 2 + 0], 2.f), 0.f);
                float d21 = fmaxf(fmaf(-2.f, acc[mi][ni][h * 2 + 1], 2.f), 0.f);
                int a_l = al[mi][h];
                if (fl0 >= 0) {
                    if (fl0 == a_l) posm[mi][h] = fminf(posm[mi][h], d20);
                    else            negm[mi][h] = fminf(negm[mi][h], d20);
                }
                if (fl1 >= 0) {
                    if (fl1 == a_l) posm[mi][h] = fminf(posm[mi][h], d21);
                    else            negm[mi][h] = fminf(negm[mi][h], d21);
                }
            }
        }
    }
    #pragma unroll
    for (int o = 1; o < 4; o <<= 1) {
        #pragma unroll
        for (int mi = 0; mi < 4; mi++)
            #pragma unroll
            for (int h = 0; h < 2; h++) {
                posm[mi][h] = fminf(posm[mi][h],
                                    __shfl_xor_sync(0xffffffffu, posm[mi][h], o));
                negm[mi][h] = fminf(negm[mi][h],
                                    __shfl_xor_sync(0xffffffffu, negm[mi][h], o));
            }
    }
    if (qlane == 0) {
        #pragma unroll
        for (int mi = 0; mi < 4; mi++)
            #pragma unroll
            for (int h = 0; h < 2; h++) {
                int a_ = by * BM + wm + mi * 16 + qid + h * 8;
                if (a_ < NA) {
                    atomicMin(&g_posBits[a_], __float_as_uint(posm[mi][h]));
                    atomicMin(&g_negBits[a_], __float_as_uint(negm[mi][h]));
                }
            }
    }
}

// ---- K5: finalize --------------------------------------------------------
__global__ void k5_finalize(float* __restrict__ out) {
    int n = g_aCnt;
    int tid = threadIdx.x;
    float sum = 0.f, cnt = 0.f;
    for (int i = tid; i < n; i += blockDim.x) {
        unsigned pb = g_posBits[i];
        unsigned nb = g_negBits[i];
        if (pb < INFBITS && nb < INFBITS) {
            float tl = fmaxf(sqrtf(__uint_as_float(pb)) -
                             sqrtf(__uint_as_float(nb)) + 0.3f, 0.f);
            sum += tl;
            cnt += 1.f;
        }
    }
    __shared__ float rs[8], rc[8];
    #pragma unroll
    for (int o = 16; o; o >>= 1) {
        sum += __shfl_xor_sync(0xffffffffu, sum, o);
        cnt += __shfl_xor_sync(0xffffffffu, cnt, o);
    }
    if ((tid & 31) == 0) { rs[tid >> 5] = sum; rc[tid >> 5] = cnt; }
    __syncthreads();
    if (tid == 0) {
        float s = 0.f, c = 0.f;
        #pragma unroll
        for (int w = 0; w < 8; w++) { s += rs[w]; c += rc[w]; }
        out[0] = (c > 0.f) ? s / fmaxf(c, 1.f) : 0.f;
    }
}

// ---------------------------------------------------------------------------
extern "C" void kernel_launch(void* const* d_in, const int* in_sizes, int n_in,
                              void* d_out, int out_size) {
    const float* feat  = (const float*)d_in[0];
    const void* labels = d_in[1];
    const void* doms   = d_in[2];
    int B = in_sizes[1];
    int D = in_sizes[0] / B;

    static int smem_set = 0;
    if (!smem_set) {
        cudaFuncSetAttribute(k4_mma_min,
                             cudaFuncAttributeMaxDynamicSharedMemorySize,
                             SMEM4_BYTES);
        smem_set = 1;
    }

    k0_reset<<<1, 1>>>();
    k1_init_detect<<<(B + 255) / 256, 256>>>((const unsigned*)labels, B);
    k2_partition<<<(B + 255) / 256, 256>>>(labels, doms, B);
    k3_normalize<<<dim3((B + 7) / 8, 2), 256>>>(feat, D);
    dim3 grid((B + BN - 1) / BN, (B + BM - 1) / BM);  // worst-case NA/NF
    k4_mma_min<<<grid, NTHR, SMEM4_BYTES>>>(D);
    k5_finalize<<<1, 256>>>((float*)d_out);
}

// round 14
// speedup vs baseline: 1.0051x; 1.0051x over previous
#include <cuda_runtime.h>
#include <stdint.h>

// ---------------------------------------------------------------------------
// TripletContrastiveLoss — tf32 mma.sync, 128x128 tile, occ-2, 2-stage
// cp.async (prefetch-first), permuted-K + LDS.64 fragments, PERSISTENT CTAs
// with atomic tile work-stealing (kills wave tail + ghost CTAs).
// (tcgen05 unavailable: bench PTX targets compute_103 w/o 'a'.)
// ---------------------------------------------------------------------------

#define BMAX 8192
#define DMAX 1024
#define INFBITS 0x7f800000u

#define BM 128
#define BN 128
#define BK 32
#define ASTR 40      // row stride (floats); LDS.64 half-warp banks all-distinct
#define NTHR 256
#define SAE (BM * ASTR)                    // 5120 floats per buffer
#define SMEM4_BYTES (4 * SAE * 4 + BN * 4) // 2 stages x (A+B) + labels = 82432 B

// K-permutation: each 8-float K-group stored as (k0,k4,k1,k5,k2,k6,k3,k7);
// mma fragment pair (k, k+4) sits at float offset g*8 + 2*(k%4), 8B-contiguous.
__device__ float g_A[(size_t)BMAX * DMAX];   // normalized anchors (tf32, K-permuted)
__device__ float g_F[(size_t)BMAX * DMAX];   // normalized fields  (tf32, K-permuted)
__device__ int   g_aRow[BMAX];
__device__ int   g_fRow[BMAX];
__device__ int   g_aLab[BMAX];
__device__ int   g_fLab[BMAX];
__device__ int   g_aCnt;
__device__ int   g_fCnt;
__device__ int   g_tile;                     // persistent work counter
__device__ unsigned g_posBits[BMAX];
__device__ unsigned g_negBits[BMAX];
__device__ int   g_is64;

__device__ __forceinline__ uint32_t smem_u32(const void* p) {
    uint32_t a;
    asm("{ .reg .u64 t; cvta.to.shared.u64 t, %1; cvt.u32.u64 %0, t; }"
        : "=r"(a) : "l"(p));
    return a;
}
__device__ __forceinline__ void cpa16(uint32_t dst, const void* src) {
    asm volatile("cp.async.cg.shared.global [%0], [%1], 16;"
                 :: "r"(dst), "l"(src));
}

// ---- K0: reset scalars --------------------------------------------------
__global__ void k0_reset() {
    g_aCnt = 0;
    g_fCnt = 0;
    g_tile = 0;
    g_is64 = 1;
}

// ---- K1: init min arrays + label dtype detection ------------------------
// int64 labels (<2^31): every odd 32-bit word is 0. int32: some odd word !=0.
__global__ void k1_init_detect(const unsigned* __restrict__ labw, int B) {
    int i = blockIdx.x * blockDim.x + threadIdx.x;
    if (i < B) {
        g_posBits[i] = INFBITS;
        g_negBits[i] = INFBITS;
        if ((i & 1) && labw[i] != 0u) g_is64 = 0;
    }
}

// ---- K2: partition into compact anchor/field lists ----------------------
__global__ void k2_partition(const void* __restrict__ labels,
                             const void* __restrict__ doms, int B) {
    int i = blockIdx.x * blockDim.x + threadIdx.x;
    if (i >= B) return;
    int is64 = g_is64;
    long long dom, lab;
    if (is64) {
        dom = ((const long long*)doms)[i];
        lab = ((const long long*)labels)[i];
    } else {
        dom = ((const int*)doms)[i];
        lab = ((const int*)labels)[i];
    }
    if (dom == 0) {
        int p = atomicAdd(&g_aCnt, 1);
        g_aRow[p] = i;
        g_aLab[p] = (int)lab;
    } else if (dom == 1) {
        int p = atomicAdd(&g_fCnt, 1);
        g_fRow[p] = i;
        g_fLab[p] = (int)lab;
    }
}

// ---- K3: normalize + tf32 round + K-permute, one warp per row -----------
// Coalesced reads/writes; even/odd lane pairs swap float4s via shfl so each
// lane emits the permuted float4 for its own (coalesced) output slot.
__global__ void k3_normalize(const float* __restrict__ feat, int D) {
    int side = blockIdx.y;
    int n = side ? g_fCnt : g_aCnt;
    int warp = threadIdx.x >> 5;
    int lane = threadIdx.x & 31;
    int b = blockIdx.x * 8 + warp;
    if (b >= n) return;
    int row = side ? g_fRow[b] : g_aRow[b];
    const float4* src = (const float4*)(feat + (size_t)row * D);
    uint4* dst = (uint4*)((side ? g_F : g_A) + (size_t)b * D);
    int nv = D >> 2;                  // <= 256 float4 slots

    float4 v[8];
    float s = 0.f;
    #pragma unroll
    for (int j = 0; j < 8; j++) {
        int t = lane + j * 32;
        if (t < nv) {
            v[j] = src[t];
            s += v[j].x * v[j].x + v[j].y * v[j].y +
                 v[j].z * v[j].z + v[j].w * v[j].w;
        }
    }
    #pragma unroll
    for (int o = 16; o; o >>= 1) s += __shfl_xor_sync(0xffffffffu, s, o);
    float scale = 1.f / fmaxf(sqrtf(s), 1e-12f);

    const bool even = (lane & 1) == 0;
    #pragma unroll
    for (int j = 0; j < 8; j++) {
        int t = lane + j * 32;
        if (t < nv) {
            float4 p;
            p.x = __shfl_xor_sync(0xffffffffu, v[j].x, 1);
            p.y = __shfl_xor_sync(0xffffffffu, v[j].y, 1);
            p.z = __shfl_xor_sync(0xffffffffu, v[j].z, 1);
            p.w = __shfl_xor_sync(0xffffffffu, v[j].w, 1);
            float4 e  = even ? v[j] : p;   // group k0..k3
            float4 o4 = even ? p : v[j];   // group k4..k7
            float f0 = even ? e.x : e.z;
            float f1 = even ? o4.x : o4.z;
            float f2 = even ? e.y : e.w;
            float f3 = even ? o4.y : o4.w;
            uint4 o;
            asm("cvt.rna.tf32.f32 %0, %1;" : "=r"(o.x) : "f"(f0 * scale));
            asm("cvt.rna.tf32.f32 %0, %1;" : "=r"(o.y) : "f"(f1 * scale));
            asm("cvt.rna.tf32.f32 %0, %1;" : "=r"(o.z) : "f"(f2 * scale));
            asm("cvt.rna.tf32.f32 %0, %1;" : "=r"(o.w) : "f"(f3 * scale));
            dst[t] = o;
        }
    }
}

// ---- tf32 mma.sync wrapper ------------------------------------------------
__device__ __forceinline__ void mma_tf32(float* d, uint32_t a0, uint32_t a1,
                                         uint32_t a2, uint32_t a3,
                                         uint32_t b0, uint32_t b1) {
    asm volatile(
        "mma.sync.aligned.m16n8k8.row.col.f32.tf32.tf32.f32 "
        "{%0,%1,%2,%3}, {%4,%5,%6,%7}, {%8,%9}, {%0,%1,%2,%3};"
        : "+f"(d[0]), "+f"(d[1]), "+f"(d[2]), "+f"(d[3])
        : "r"(a0), "r"(a1), "r"(a2), "r"(a3), "r"(b0), "r"(b1));
}

// ---- K4: persistent HMMA tf32 GEMM + fused masked min --------------------
// 8 warps: warp grid 2(M)x4(N), warp tile 64x32 = 4x4 m16n8k8 atoms.
// Per chunk (R10 proven ordering): prefetch c+1 -> commit -> wait 1 -> sync
// -> compute c -> sync. Tiles pulled from g_tile atomic counter.
__global__ void __launch_bounds__(NTHR, 2)
k4_mma_min(int D) {
    extern __shared__ float smem[];
    float* sA = smem;              // [2][SAE]
    float* sB = smem + 2 * SAE;    // [2][SAE]
    int* sFlab = (int*)(smem + 4 * SAE);
    __shared__ int sTile;

    const int NA = g_aCnt;
    const int NF = g_fCnt;
    const int nbx = (NF + BN - 1) / BN;
    const int nby = (NA + BM - 1) / BM;
    const int ntiles = nbx * nby;

    const int tid = threadIdx.x;
    const int wid = tid >> 5;
    const int lane = tid & 31;
    const int qid = lane >> 2;
    const int qlane = lane & 3;
    const int wm = (wid & 1) * 64;
    const int wn = (wid >> 1) * 32;

    const int m0 = tid >> 3;        // 0..31
    const int q4 = (tid & 7) * 4;   // 0,4,...,28 (floats)
    const uint32_t sa0 = smem_u32(sA);
    const uint32_t sb0 = smem_u32(sB);
    const uint32_t dstOff = (uint32_t)((m0 * ASTR + q4) * 4);
    const int nch = D >> 5;

    for (;;) {
        if (tid == 0) sTile = atomicAdd(&g_tile, 1);
        __syncthreads();                 // sTile visible; prev tile's sFlab reads done
        const int t = sTile;
        if (t >= ntiles) break;
        const int bx = t % nbx;
        const int by = t / nbx;

        if (tid < BN) {
            int f = bx * BN + tid;
            sFlab[tid] = (f < NF) ? g_fLab[f] : -1;
        }

        // epilogue labels hoisted before the mainloop
        int al[4][2];
        #pragma unroll
        for (int mi = 0; mi < 4; mi++)
            #pragma unroll
            for (int h = 0; h < 2; h++) {
                int a_ = by * BM + wm + mi * 16 + qid + h * 8;
                al[mi][h] = (a_ < NA) ? g_aLab[a_] : -2;
            }

        int aRowG[4], bRowG[4];
        #pragma unroll
        for (int it = 0; it < 4; it++) {
            int ga = by * BM + m0 + 32 * it;
            aRowG[it] = (ga < NA) ? ga : NA - 1;   // clamp; rows >= NA unused
            int gf = bx * BN + m0 + 32 * it;
            bRowG[it] = (gf < NF) ? gf : NF - 1;   // clamp; excluded via sFlab
        }

        float acc[4][4][4];
        #pragma unroll
        for (int mi = 0; mi < 4; mi++)
            #pragma unroll
            for (int ni = 0; ni < 4; ni++)
                #pragma unroll
                for (int r = 0; r < 4; r++) acc[mi][ni][r] = 0.f;

        // prefetch chunk 0 -> buffer 0
        #pragma unroll
        for (int it = 0; it < 4; it++) {
            cpa16(sa0 + dstOff + it * (32 * ASTR * 4),
                  &g_A[(size_t)aRowG[it] * D + q4]);
            cpa16(sb0 + dstOff + it * (32 * ASTR * 4),
                  &g_F[(size_t)bRowG[it] * D + q4]);
        }
        asm volatile("cp.async.commit_group;");

        for (int c = 0; c < nch; c++) {
            const int cur = c & 1;
            if (c + 1 < nch) {
                const int nb = (c + 1) & 1;
                const int ko = (c + 1) << 5;
                #pragma unroll
                for (int it = 0; it < 4; it++) {
                    cpa16(sa0 + nb * (SAE * 4) + dstOff + it * (32 * ASTR * 4),
                          &g_A[(size_t)aRowG[it] * D + q4 + ko]);
                    cpa16(sb0 + nb * (SAE * 4) + dstOff + it * (32 * ASTR * 4),
                          &g_F[(size_t)bRowG[it] * D + q4 + ko]);
                }
                asm volatile("cp.async.commit_group;");
                asm volatile("cp.async.wait_group 1;");
            } else {
                asm volatile("cp.async.wait_group 0;");
            }
            __syncthreads();

            const float* cA = sA + cur * SAE;
            const float* cB = sB + cur * SAE;
            #pragma unroll
            for (int g = 0; g < 4; g++) {
                const int kb2 = g * 8 + 2 * qlane;    // permuted offset of (k, k+4)
                uint32_t a[4][4], b[4][2];
                #pragma unroll
                for (int mi = 0; mi < 4; mi++) {
                    const float* pr = cA + (wm + mi * 16 + qid) * ASTR + kb2;
                    uint2 lo = *(const uint2*)pr;                  // a0, a2
                    uint2 hi = *(const uint2*)(pr + 8 * ASTR);     // a1, a3
                    a[mi][0] = lo.x; a[mi][1] = hi.x;
                    a[mi][2] = lo.y; a[mi][3] = hi.y;
                }
                #pragma unroll
                for (int ni = 0; ni < 4; ni++) {
                    const float* pr = cB + (wn + ni * 8 + qid) * ASTR + kb2;
                    uint2 bb = *(const uint2*)pr;                  // b0, b1
                    b[ni][0] = bb.x; b[ni][1] = bb.y;
                }
                #pragma unroll
                for (int mi = 0; mi < 4; mi++)
                    #pragma unroll
                    for (int ni = 0; ni < 4; ni++)
                        mma_tf32(acc[mi][ni], a[mi][0], a[mi][1], a[mi][2],
                                 a[mi][3], b[ni][0], b[ni][1]);
            }
            __syncthreads();   // fragment reads done before buffer reuse
        }

        // --- epilogue: d^2 = max(2 - 2*dot, 0), masked min per anchor row --
        float posm[4][2], negm[4][2];
        #pragma unroll
        for (int mi = 0; mi < 4; mi++)
            #pragma unroll
            for (int h = 0; h < 2; h++) {
                posm[mi][h] = __uint_as_float(INFBITS);
                negm[mi][h] = posm[mi][h];
            }

        #pragma unroll
        for (int mi = 0; mi < 4; mi++) {
            #pragma unroll
            for (int ni = 0; ni < 4; ni++) {
                int n0 = wn + ni * 8 + 2 * qlane;
                int fl0 = sFlab[n0];
                int fl1 = sFlab[n0 + 1];
                #pragma unroll
                for (int h = 0; h < 2; h++) {
                    float d20 = fmaxf(fmaf(-2.f, acc[mi][ni][h * 2 + 0], 2.f), 0.f);
                    float d21 = fmaxf(fmaf(-2.f, acc[mi][ni][h * 2 + 1], 2.f), 0.f);
                    int a_l = al[mi][h];
                    if (fl0 >= 0) {
                        if (fl0 == a_l) posm[mi][h] = fminf(posm[mi][h], d20);
                        else            negm[mi][h] = fminf(negm[mi][h], d20);
                    }
                    if (fl1 >= 0) {
                        if (fl1 == a_l) posm[mi][h] = fminf(posm[mi][h], d21);
                        else            negm[mi][h] = fminf(negm[mi][h], d21);
                    }
                }
            }
        }
        #pragma unroll
        for (int o = 1; o < 4; o <<= 1) {
            #pragma unroll
            for (int mi = 0; mi < 4; mi++)
                #pragma unroll
                for (int h = 0; h < 2; h++) {
                    posm[mi][h] = fminf(posm[mi][h],
                                        __shfl_xor_sync(0xffffffffu, posm[mi][h], o));
                    negm[mi][h] = fminf(negm[mi][h],
                                        __shfl_xor_sync(0xffffffffu, negm[mi][h], o));
                }
        }
        if (qlane == 0) {
            #pragma unroll
            for (int mi = 0; mi < 4; mi++)
                #pragma unroll
                for (int h = 0; h < 2; h++) {
                    int a_ = by * BM + wm + mi * 16 + qid + h * 8;
                    if (a_ < NA) {
                        atomicMin(&g_posBits[a_], __float_as_uint(posm[mi][h]));
                        atomicMin(&g_negBits[a_], __float_as_uint(negm[mi][h]));
                    }
                }
        }
    }
}

// ---- K5: finalize --------------------------------------------------------
__global__ void k5_finalize(float* __restrict__ out) {
    int n = g_aCnt;
    int tid = threadIdx.x;
    float sum = 0.f, cnt = 0.f;
    for (int i = tid; i < n; i += blockDim.x) {
        unsigned pb = g_posBits[i];
        unsigned nb = g_negBits[i];
        if (pb < INFBITS && nb < INFBITS) {
            float tl = fmaxf(sqrtf(__uint_as_float(pb)) -
                             sqrtf(__uint_as_float(nb)) + 0.3f, 0.f);
            sum += tl;
            cnt += 1.f;
        }
    }
    __shared__ float rs[8], rc[8];
    #pragma unroll
    for (int o = 16; o; o >>= 1) {
        sum += __shfl_xor_sync(0xffffffffu, sum, o);
        cnt += __shfl_xor_sync(0xffffffffu, cnt, o);
    }
    if ((tid & 31) == 0) { rs[tid >> 5] = sum; rc[tid >> 5] = cnt; }
    __syncthreads();
    if (tid == 0) {
        float s = 0.f, c = 0.f;
        #pragma unroll
        for (int w = 0; w < 8; w++) { s += rs[w]; c += rc[w]; }
        out[0] = (c > 0.f) ? s / fmaxf(c, 1.f) : 0.f;
    }
}

// ---------------------------------------------------------------------------
extern "C" void kernel_launch(void* const* d_in, const int* in_sizes, int n_in,
                              void* d_out, int out_size) {
    const float* feat  = (const float*)d_in[0];
    const void* labels = d_in[1];
    const void* doms   = d_in[2];
    int B = in_sizes[1];
    int D = in_sizes[0] / B;

    static int nCta = 0;
    if (!nCta) {
        cudaFuncSetAttribute(k4_mma_min,
                             cudaFuncAttributeMaxDynamicSharedMemorySize,
                             SMEM4_BYTES);
        int dev = 0, sms = 148;
        cudaGetDevice(&dev);
        cudaDeviceGetAttribute(&sms, cudaDevAttrMultiProcessorCount, dev);
        nCta = 2 * sms;
    }

    k0_reset<<<1, 1>>>();
    k1_init_detect<<<(B + 255) / 256, 256>>>((const unsigned*)labels, B);
    k2_partition<<<(B + 255) / 256, 256>>>(labels, doms, B);
    k3_normalize<<<dim3((B + 7) / 8, 2), 256>>>(feat, D);
    k4_mma_min<<<nCta, NTHR, SMEM4_BYTES>>>(D);
    k5_finalize<<<1, 256>>>((float*)d_out);
}

// round 16
// speedup vs baseline: 2.3215x; 2.3098x over previous
#include <cuda_runtime.h>
#include <stdint.h>

// ---------------------------------------------------------------------------
// TripletContrastiveLoss — bf16 mma.sync m16n8k16, 128x128 tile, occ-2,
// 2-stage cp.async (prefetch-first, R10 structure verbatim), permuted
// pair-unit layout + LDS.64 fragments.
// (tcgen05 unavailable: bench PTX targets compute_103 w/o 'a'.)
// ---------------------------------------------------------------------------

#define BMAX 8192
#define DMAX 1024
#define INFBITS 0x7f800000u

#define BM 128
#define BN 128
#define ASTRW 40     // stage row stride in u32 words; LDS.64 banks all-distinct
#define NTHR 256
#define STGB (BM * ASTRW * 4)              // 20480 B per matrix per stage
#define SMEM4_BYTES (4 * STGB + BN * 4)    // 2 stages x (A+B) + labels = 82432 B

// Pair-unit permutation: each k16 group = 8 bf16x2 units, stored in order
// (0,4,1,5,2,6,3,7). Fragment pair (unit c, unit c+4) is then 8B-contiguous
// at word offset g*8 + 2*c for k16-group g. rows: bf16, D elems = D/2 words.
__device__ uint32_t g_Ab[(size_t)BMAX * (DMAX / 2)];  // anchors (bf16x2 units)
__device__ uint32_t g_Fb[(size_t)BMAX * (DMAX / 2)];  // fields
__device__ int   g_aRow[BMAX];
__device__ int   g_fRow[BMAX];
__device__ int   g_aLab[BMAX];
__device__ int   g_fLab[BMAX];
__device__ int   g_aCnt;
__device__ int   g_fCnt;
__device__ unsigned g_posBits[BMAX];
__device__ unsigned g_negBits[BMAX];
__device__ int   g_is64;

__device__ __forceinline__ uint32_t smem_u32(const void* p) {
    uint32_t a;
    asm("{ .reg .u64 t; cvta.to.shared.u64 t, %1; cvt.u32.u64 %0, t; }"
        : "=r"(a) : "l"(p));
    return a;
}
__device__ __forceinline__ void cpa16(uint32_t dst, const void* src) {
    asm volatile("cp.async.cg.shared.global [%0], [%1], 16;"
                 :: "r"(dst), "l"(src));
}

// ---- K0: reset scalars --------------------------------------------------
__global__ void k0_reset() {
    g_aCnt = 0;
    g_fCnt = 0;
    g_is64 = 1;
}

// ---- K1: init min arrays + label dtype detection ------------------------
// int64 labels (<2^31): every odd 32-bit word is 0. int32: some odd word !=0.
__global__ void k1_init_detect(const unsigned* __restrict__ labw, int B) {
    int i = blockIdx.x * blockDim.x + threadIdx.x;
    if (i < B) {
        g_posBits[i] = INFBITS;
        g_negBits[i] = INFBITS;
        if ((i & 1) && labw[i] != 0u) g_is64 = 0;
    }
}

// ---- K2: partition into compact anchor/field lists ----------------------
__global__ void k2_partition(const void* __restrict__ labels,
                             const void* __restrict__ doms, int B) {
    int i = blockIdx.x * blockDim.x + threadIdx.x;
    if (i >= B) return;
    int is64 = g_is64;
    long long dom, lab;
    if (is64) {
        dom = ((const long long*)doms)[i];
        lab = ((const long long*)labels)[i];
    } else {
        dom = ((const int*)doms)[i];
        lab = ((const int*)labels)[i];
    }
    if (dom == 0) {
        int p = atomicAdd(&g_aCnt, 1);
        g_aRow[p] = i;
        g_aLab[p] = (int)lab;
    } else if (dom == 1) {
        int p = atomicAdd(&g_fCnt, 1);
        g_fRow[p] = i;
        g_fLab[p] = (int)lab;
    }
}

// ---- K3: normalize + bf16 round + pair-unit permute, one warp per row ----
// Lane t (float4 index) produces units 2t, 2t+1 of its row; dest positions
// inside the unit's k16 group follow the (0,4,1,5,2,6,3,7) permutation.
__global__ void k3_normalize(const float* __restrict__ feat, int D) {
    int side = blockIdx.y;
    int n = side ? g_fCnt : g_aCnt;
    int warp = threadIdx.x >> 5;
    int lane = threadIdx.x & 31;
    int b = blockIdx.x * 8 + warp;
    if (b >= n) return;
    int row = side ? g_fRow[b] : g_aRow[b];
    const float4* src = (const float4*)(feat + (size_t)row * D);
    uint32_t* dst = (side ? g_Fb : g_Ab) + (size_t)b * (D >> 1);
    int nv = D >> 2;                  // <= 256 float4 slots

    float4 v[8];
    float s = 0.f;
    #pragma unroll
    for (int j = 0; j < 8; j++) {
        int t = lane + j * 32;
        if (t < nv) {
            v[j] = src[t];
            s += v[j].x * v[j].x + v[j].y * v[j].y +
                 v[j].z * v[j].z + v[j].w * v[j].w;
        }
    }
    #pragma unroll
    for (int o = 16; o; o >>= 1) s += __shfl_xor_sync(0xffffffffu, s, o);
    float scale = 1.f / fmaxf(sqrtf(s), 1e-12f);

    #pragma unroll
    for (int j = 0; j < 8; j++) {
        int t = lane + j * 32;
        if (t < nv) {
            // pack (low = even k, high = odd k)
            uint32_t w0, w1;
            asm("cvt.rn.bf16x2.f32 %0, %1, %2;"
                : "=r"(w0) : "f"(v[j].y * scale), "f"(v[j].x * scale));
            asm("cvt.rn.bf16x2.f32 %0, %1, %2;"
                : "=r"(w1) : "f"(v[j].w * scale), "f"(v[j].z * scale));
            int grp = t >> 2;                  // k16 group
            int u0 = (2 * t) & 7;
            int u1 = (2 * t + 1) & 7;
            int p0 = (u0 < 4) ? (2 * u0) : (2 * u0 - 7);
            int p1 = (u1 < 4) ? (2 * u1) : (2 * u1 - 7);
            dst[(grp << 3) + p0] = w0;
            dst[(grp << 3) + p1] = w1;
        }
    }
}

// ---- bf16 mma.sync wrapper ------------------------------------------------
__device__ __forceinline__ void mma_bf16(float* d, uint32_t a0, uint32_t a1,
                                         uint32_t a2, uint32_t a3,
                                         uint32_t b0, uint32_t b1) {
    asm volatile(
        "mma.sync.aligned.m16n8k16.row.col.f32.bf16.bf16.f32 "
        "{%0,%1,%2,%3}, {%4,%5,%6,%7}, {%8,%9}, {%0,%1,%2,%3};"
        : "+f"(d[0]), "+f"(d[1]), "+f"(d[2]), "+f"(d[3])
        : "r"(a0), "r"(a1), "r"(a2), "r"(a3), "r"(b0), "r"(b1));
}

// ---- K4: 128x128 bf16 HMMA GEMM, cp.async double buffer, fused min -------
// 8 warps: warp grid 2(M)x4(N), warp tile 64x32 = 4x4 m16n8k16 atoms.
// Per chunk (K=64 elems = 128B/row): prefetch c+1 -> commit -> wait 1 ->
// sync -> compute c -> sync.  (R10 proven ordering.)
__global__ void __launch_bounds__(NTHR, 2)
k4_mma_min(int D) {
    extern __shared__ uint32_t smem[];
    uint32_t* sA = smem;                       // [2][BM*ASTRW]
    uint32_t* sB = smem + 2 * (BM * ASTRW);    // [2][BM*ASTRW]
    int* sFlab = (int*)(smem + 4 * (BM * ASTRW));

    const int NA = g_aCnt;
    const int NF = g_fCnt;
    const int by = blockIdx.y, bx = blockIdx.x;
    if (by * BM >= NA || bx * BN >= NF) return;

    const int tid = threadIdx.x;
    const int wid = tid >> 5;
    const int lane = tid & 31;
    const int qid = lane >> 2;
    const int qlane = lane & 3;
    const int wm = (wid & 1) * 64;
    const int wn = (wid >> 1) * 32;

    if (tid < BN) {
        int f = bx * BN + tid;
        sFlab[tid] = (f < NF) ? g_fLab[f] : -1;
    }

    // epilogue labels hoisted before the mainloop
    int al[4][2];
    #pragma unroll
    for (int mi = 0; mi < 4; mi++)
        #pragma unroll
        for (int h = 0; h < 2; h++) {
            int a_ = by * BM + wm + mi * 16 + qid + h * 8;
            al[mi][h] = (a_ < NA) ? g_aLab[a_] : -2;
        }

    // load geometry: thread covers rows m0+32*it (it=0..3), 16B word col q4
    const int m0 = tid >> 3;          // 0..31
    const int q4 = (tid & 7) * 4;     // u32 word offset 0,4,...,28
    const int rw = D >> 1;            // u32 words per global row
    int aRowG[4], bRowG[4];
    #pragma unroll
    for (int it = 0; it < 4; it++) {
        int ga = by * BM + m0 + 32 * it;
        aRowG[it] = (ga < NA) ? ga : NA - 1;   // clamp; rows >= NA unused
        int gf = bx * BN + m0 + 32 * it;
        bRowG[it] = (gf < NF) ? gf : NF - 1;   // clamp; excluded via sFlab
    }
    const uint32_t sa0 = smem_u32(sA);
    const uint32_t sb0 = smem_u32(sB);
    const uint32_t dstOff = (uint32_t)((m0 * ASTRW + q4) * 4);

    float acc[4][4][4];
    #pragma unroll
    for (int mi = 0; mi < 4; mi++)
        #pragma unroll
        for (int ni = 0; ni < 4; ni++)
            #pragma unroll
            for (int r = 0; r < 4; r++) acc[mi][ni][r] = 0.f;

    const int nch = D >> 6;           // chunks of 64 bf16 (32 words, 128B)

    // prefetch chunk 0 -> buffer 0
    #pragma unroll
    for (int it = 0; it < 4; it++) {
        cpa16(sa0 + dstOff + it * (32 * ASTRW * 4),
              &g_Ab[(size_t)aRowG[it] * rw + q4]);
        cpa16(sb0 + dstOff + it * (32 * ASTRW * 4),
              &g_Fb[(size_t)bRowG[it] * rw + q4]);
    }
    asm volatile("cp.async.commit_group;");

    for (int c = 0; c < nch; c++) {
        const int cur = c & 1;
        if (c + 1 < nch) {
            const int nb = (c + 1) & 1;
            const int ko = (c + 1) << 5;          // word offset of next chunk
            #pragma unroll
            for (int it = 0; it < 4; it++) {
                cpa16(sa0 + nb * STGB + dstOff + it * (32 * ASTRW * 4),
                      &g_Ab[(size_t)aRowG[it] * rw + q4 + ko]);
                cpa16(sb0 + nb * STGB + dstOff + it * (32 * ASTRW * 4),
                      &g_Fb[(size_t)bRowG[it] * rw + q4 + ko]);
            }
            asm volatile("cp.async.commit_group;");
            asm volatile("cp.async.wait_group 1;");
        } else {
            asm volatile("cp.async.wait_group 0;");
        }
        __syncthreads();

        const uint32_t* cA = sA + cur * (BM * ASTRW);
        const uint32_t* cB = sB + cur * (BM * ASTRW);
        #pragma unroll
        for (int g = 0; g < 4; g++) {             // 4 k16-groups per chunk
            const int kb2 = g * 8 + 2 * qlane;    // permuted units (c, c+4)
            uint32_t a[4][4], b[4][2];
            #pragma unroll
            for (int mi = 0; mi < 4; mi++) {
                const uint32_t* pr = cA + (wm + mi * 16 + qid) * ASTRW + kb2;
                uint2 lo = *(const uint2*)pr;                  // a0, a2
                uint2 hi = *(const uint2*)(pr + 8 * ASTRW);    // a1, a3
                a[mi][0] = lo.x; a[mi][1] = hi.x;
                a[mi][2] = lo.y; a[mi][3] = hi.y;
            }
            #pragma unroll
            for (int ni = 0; ni < 4; ni++) {
                const uint32_t* pr = cB + (wn + ni * 8 + qid) * ASTRW + kb2;
                uint2 bb = *(const uint2*)pr;                  // b0, b1
                b[ni][0] = bb.x; b[ni][1] = bb.y;
            }
            #pragma unroll
            for (int mi = 0; mi < 4; mi++)
                #pragma unroll
                for (int ni = 0; ni < 4; ni++)
                    mma_bf16(acc[mi][ni], a[mi][0], a[mi][1], a[mi][2],
                             a[mi][3], b[ni][0], b[ni][1]);
        }
        __syncthreads();   // fragment reads done before buffer reuse
    }

    // --- epilogue: d^2 = max(2 - 2*dot, 0), masked min per anchor row ----
    float posm[4][2], negm[4][2];
    #pragma unroll
    for (int mi = 0; mi < 4; mi++)
        #pragma unroll
        for (int h = 0; h < 2; h++) {
            posm[mi][h] = __uint_as_float(INFBITS);
            negm[mi][h] = posm[mi][h];
        }

    #pragma unroll
    for (int mi = 0; mi < 4; mi++) {
        #pragma unroll
        for (int ni = 0; ni < 4; ni++) {
            int n0 = wn + ni * 8 + 2 * qlane;
            int fl0 = sFlab[n0];
            int fl1 = sFlab[n0 + 1];
            #pragma unroll
            for (int h = 0; h < 2; h++) {
                float d20 = fmaxf(fmaf(-2.f, acc[mi][ni][h * 2 + 0], 2.f), 0.f);
                float d21 = fmaxf(fmaf(-2.f, acc[mi][ni][h * 2 + 1], 2.f), 0.f);
                int a_l = al[mi][h];
                if (fl0 >= 0) {
                    if (fl0 == a_l) posm[mi][h] = fminf(posm[mi][h], d20);
                    else            negm[mi][h] = fminf(negm[mi][h], d20);
                }
                if (fl1 >= 0) {
                    if (fl1 == a_l) posm[mi][h] = fminf(posm[mi][h], d21);
                    else            negm[mi][h] = fminf(negm[mi][h], d21);
                }
            }
        }
    }
    #pragma unroll
    for (int o = 1; o < 4; o <<= 1) {
        #pragma unroll
        for (int mi = 0; mi < 4; mi++)
            #pragma unroll
            for (int h = 0; h < 2; h++) {
                posm[mi][h] = fminf(posm[mi][h],
                                    __shfl_xor_sync(0xffffffffu, posm[mi][h], o));
                negm[mi][h] = fminf(negm[mi][h],
                                    __shfl_xor_sync(0xffffffffu, negm[mi][h], o));
            }
    }
    if (qlane == 0) {
        #pragma unroll
        for (int mi = 0; mi < 4; mi++)
            #pragma unroll
            for (int h = 0; h < 2; h++) {
                int a_ = by * BM + wm + mi * 16 + qid + h * 8;
                if (a_ < NA) {
                    atomicMin(&g_posBits[a_], __float_as_uint(posm[mi][h]));
                    atomicMin(&g_negBits[a_], __float_as_uint(negm[mi][h]));
                }
            }
    }
}

// ---- K5: finalize --------------------------------------------------------
__global__ void k5_finalize(float* __restrict__ out) {
    int n = g_aCnt;
    int tid = threadIdx.x;
    float sum = 0.f, cnt = 0.f;
    for (int i = tid; i < n; i += blockDim.x) {
        unsigned pb = g_posBits[i];
        unsigned nb = g_negBits[i];
        if (pb < INFBITS && nb < INFBITS) {
            float tl = fmaxf(sqrtf(__uint_as_float(pb)) -
                             sqrtf(__uint_as_float(nb)) + 0.3f, 0.f);
            sum += tl;
            cnt += 1.f;
        }
    }
    __shared__ float rs[8], rc[8];
    #pragma unroll
    for (int o = 16; o; o >>= 1) {
        sum += __shfl_xor_sync(0xffffffffu, sum, o);
        cnt += __shfl_xor_sync(0xffffffffu, cnt, o);
    }
    if ((tid & 31) == 0) { rs[tid >> 5] = sum; rc[tid >> 5] = cnt; }
    __syncthreads();
    if (tid == 0) {
        float s = 0.f, c = 0.f;
        #pragma unroll
        for (int w = 0; w < 8; w++) { s += rs[w]; c += rc[w]; }
        out[0] = (c > 0.f) ? s / fmaxf(c, 1.f) : 0.f;
    }
}

// ---------------------------------------------------------------------------
extern "C" void kernel_launch(void* const* d_in, const int* in_sizes, int n_in,
                              void* d_out, int out_size) {
    const float* feat  = (const float*)d_in[0];
    const void* labels = d_in[1];
    const void* doms   = d_in[2];
    int B = in_sizes[1];
    int D = in_sizes[0] / B;

    static int smem_set = 0;
    if (!smem_set) {
        cudaFuncSetAttribute(k4_mma_min,
                             cudaFuncAttributeMaxDynamicSharedMemorySize,
                             SMEM4_BYTES);
        smem_set = 1;
    }

    k0_reset<<<1, 1>>>();
    k1_init_detect<<<(B + 255) / 256, 256>>>((const unsigned*)labels, B);
    k2_partition<<<(B + 255) / 256, 256>>>(labels, doms, B);
    k3_normalize<<<dim3((B + 7) / 8, 2), 256>>>(feat, D);
    dim3 grid((B + BN - 1) / BN, (B + BM - 1) / BM);  // worst-case NA/NF
    k4_mma_min<<<grid, NTHR, SMEM4_BYTES>>>(D);
    k5_finalize<<<1, 256>>>((float*)d_out);
}